// round 1
// baseline (speedup 1.0000x reference)
#include <cuda_runtime.h>

// Problem constants
#define BATCHX 8
#define NSEQ   1024
#define EMBD   1024
#define HEADS  16
#define DHEAD  64
#define KDIM   1024
#define MROWS  (BATCHX * NSEQ)   // 8192

// Scratch (device globals: allocation-free per harness rules)
__device__ float g_q[BATCHX * HEADS * NSEQ * DHEAD];
__device__ float g_k[BATCHX * HEADS * NSEQ * DHEAD];
__device__ float g_v[BATCHX * HEADS * NSEQ * DHEAD];
__device__ float g_att[MROWS * EMBD];

// ---------------------------------------------------------------------------
// GEMM1: qkv = x @ W_qkv^T, scatter into per-head Q (pre-scaled), K, V
// C[m, c] = sum_k A[m,k] * W[c,k]; M=8192, N=3072, K=1024
// 128x128 block tile, BK=8, 256 threads, 8x8 per thread, reg-prefetch.
// ---------------------------------------------------------------------------
__global__ __launch_bounds__(256) void qkv_gemm(const float* __restrict__ A,
                                                const float* __restrict__ W) {
    __shared__ float As[8][132];
    __shared__ float Bs[8][132];
    const int tid = threadIdx.x;
    const int m0 = blockIdx.y * 128;
    const int n0 = blockIdx.x * 128;
    const int lr = tid >> 1;            // 0..127
    const int lk = (tid & 1) << 2;      // 0 or 4
    const float* aptr = A + (size_t)(m0 + lr) * KDIM + lk;
    const float* bptr = W + (size_t)(n0 + lr) * KDIM + lk;
    const int ty = tid >> 4, tx = tid & 15;

    float acc[8][8];
#pragma unroll
    for (int i = 0; i < 8; i++)
#pragma unroll
        for (int j = 0; j < 8; j++) acc[i][j] = 0.f;

    float4 apre = *(const float4*)aptr;
    float4 bpre = *(const float4*)bptr;

    for (int k0 = 0; k0 < KDIM; k0 += 8) {
        __syncthreads();
        As[lk + 0][lr] = apre.x; As[lk + 1][lr] = apre.y;
        As[lk + 2][lr] = apre.z; As[lk + 3][lr] = apre.w;
        Bs[lk + 0][lr] = bpre.x; Bs[lk + 1][lr] = bpre.y;
        Bs[lk + 2][lr] = bpre.z; Bs[lk + 3][lr] = bpre.w;
        __syncthreads();
        if (k0 + 8 < KDIM) {
            apre = *(const float4*)(aptr + k0 + 8);
            bpre = *(const float4*)(bptr + k0 + 8);
        }
#pragma unroll
        for (int kk = 0; kk < 8; kk++) {
            float af[8], bf[8];
            *(float4*)&af[0] = *(const float4*)&As[kk][ty * 8];
            *(float4*)&af[4] = *(const float4*)&As[kk][ty * 8 + 4];
            *(float4*)&bf[0] = *(const float4*)&Bs[kk][tx * 8];
            *(float4*)&bf[4] = *(const float4*)&Bs[kk][tx * 8 + 4];
#pragma unroll
            for (int i = 0; i < 8; i++)
#pragma unroll
                for (int j = 0; j < 8; j++) acc[i][j] += af[i] * bf[j];
        }
    }

    // Scatter epilogue: column c -> (q/k/v, head, dim); Q pre-scaled by D^-0.5
#pragma unroll
    for (int i = 0; i < 8; i++) {
        const int m = m0 + ty * 8 + i;
        const int b = m >> 10;
        const int n = m & 1023;
#pragma unroll
        for (int j = 0; j < 8; j++) {
            const int c = n0 + tx * 8 + j;
            const int t = c >> 10;       // 0=q 1=k 2=v
            const int e = c & 1023;
            const int h = e >> 6;
            const int d = e & 63;
            const size_t off = ((size_t)((b * HEADS + h) * NSEQ) + n) * DHEAD + d;
            const float v = acc[i][j];
            if (t == 0)      g_q[off] = v * 0.125f;   // SCALE = 64^-0.5
            else if (t == 1) g_k[off] = v;
            else             g_v[off] = v;
        }
    }
}

// ---------------------------------------------------------------------------
// GEMM2: out = g_att @ W_out^T + b_out; M=8192, N=1024, K=1024
// ---------------------------------------------------------------------------
__global__ __launch_bounds__(256) void out_gemm(const float* __restrict__ W,
                                                const float* __restrict__ bias,
                                                float* __restrict__ out) {
    __shared__ float As[8][132];
    __shared__ float Bs[8][132];
    const float* A = g_att;
    const int tid = threadIdx.x;
    const int m0 = blockIdx.y * 128;
    const int n0 = blockIdx.x * 128;
    const int lr = tid >> 1;
    const int lk = (tid & 1) << 2;
    const float* aptr = A + (size_t)(m0 + lr) * KDIM + lk;
    const float* bptr = W + (size_t)(n0 + lr) * KDIM + lk;
    const int ty = tid >> 4, tx = tid & 15;

    float acc[8][8];
#pragma unroll
    for (int i = 0; i < 8; i++)
#pragma unroll
        for (int j = 0; j < 8; j++) acc[i][j] = 0.f;

    float4 apre = *(const float4*)aptr;
    float4 bpre = *(const float4*)bptr;

    for (int k0 = 0; k0 < KDIM; k0 += 8) {
        __syncthreads();
        As[lk + 0][lr] = apre.x; As[lk + 1][lr] = apre.y;
        As[lk + 2][lr] = apre.z; As[lk + 3][lr] = apre.w;
        Bs[lk + 0][lr] = bpre.x; Bs[lk + 1][lr] = bpre.y;
        Bs[lk + 2][lr] = bpre.z; Bs[lk + 3][lr] = bpre.w;
        __syncthreads();
        if (k0 + 8 < KDIM) {
            apre = *(const float4*)(aptr + k0 + 8);
            bpre = *(const float4*)(bptr + k0 + 8);
        }
#pragma unroll
        for (int kk = 0; kk < 8; kk++) {
            float af[8], bf[8];
            *(float4*)&af[0] = *(const float4*)&As[kk][ty * 8];
            *(float4*)&af[4] = *(const float4*)&As[kk][ty * 8 + 4];
            *(float4*)&bf[0] = *(const float4*)&Bs[kk][tx * 8];
            *(float4*)&bf[4] = *(const float4*)&Bs[kk][tx * 8 + 4];
#pragma unroll
            for (int i = 0; i < 8; i++)
#pragma unroll
                for (int j = 0; j < 8; j++) acc[i][j] += af[i] * bf[j];
        }
    }

#pragma unroll
    for (int i = 0; i < 8; i++) {
        const int m = m0 + ty * 8 + i;
#pragma unroll
        for (int j = 0; j < 8; j += 4) {
            const int c = n0 + tx * 8 + j;
            float4 o;
            o.x = acc[i][j + 0] + bias[c + 0];
            o.y = acc[i][j + 1] + bias[c + 1];
            o.z = acc[i][j + 2] + bias[c + 2];
            o.w = acc[i][j + 3] + bias[c + 3];
            *(float4*)&out[(size_t)m * EMBD + c] = o;
        }
    }
}

// ---------------------------------------------------------------------------
// Flash-style attention with additive bias gather.
// Grid: (N/64, B*H); 256 threads = 16x16, each thread a 4x4 micro-tile.
// Online softmax state (m, l) kept redundantly per 16-lane row group; row
// reductions via __shfl_xor within 16-lane halves (warp = 2 row-groups).
// ---------------------------------------------------------------------------
#define PADT 68   // float4-friendly transposed-tile stride (conflict-free)
#define PADP 65   // scalar-access stride for P^T (aliases K^T buffer)

__global__ __launch_bounds__(256) void attn_kernel(const float* __restrict__ biases,
                                                   const int* __restrict__ idxs) {
    extern __shared__ float sm[];
    float* Qt = sm;                    // Qt[d*PADT + r]   (Q transposed)
    float* Kt = Qt + 64 * PADT;        // Kt[d*PADT + c]   (K transposed)
    float* Vs = Kt + 64 * PADT;        // Vs[c*PADT + d]
    float* Pt = Kt;                    // Pt[c*PADP + r]   aliases Kt storage

    const int tid = threadIdx.x;
    const int ty = tid >> 4, tx = tid & 15;
    const int r0 = ty << 2, c0 = tx << 2;
    const int h = blockIdx.y & 15;
    const int b = blockIdx.y >> 4;
    const int i0 = blockIdx.x << 6;

    const size_t bh = (size_t)(b * HEADS + h) * NSEQ * DHEAD;
    const float* qb = g_q + bh;
    const float* kb = g_k + bh;
    const float* vb = g_v + bh;
    const float* brow = biases + h * 1024;

    const int lr = tid & 63;
    const int ld0 = (tid >> 6) << 4;   // 0,16,32,48

    // Load Q tile transposed into shared
    {
        const float4* src = (const float4*)(qb + (size_t)(i0 + lr) * DHEAD + ld0);
#pragma unroll
        for (int u = 0; u < 4; u++) {
            float4 t4 = src[u];
            int d = ld0 + (u << 2);
            Qt[(d + 0) * PADT + lr] = t4.x;
            Qt[(d + 1) * PADT + lr] = t4.y;
            Qt[(d + 2) * PADT + lr] = t4.z;
            Qt[(d + 3) * PADT + lr] = t4.w;
        }
    }

    float acc[4][4];
#pragma unroll
    for (int i = 0; i < 4; i++)
#pragma unroll
        for (int j = 0; j < 4; j++) acc[i][j] = 0.f;
    float mrow[4], lrow[4];
#pragma unroll
    for (int i = 0; i < 4; i++) { mrow[i] = -1e30f; lrow[i] = 0.f; }

    for (int j0 = 0; j0 < NSEQ; j0 += 64) {
        __syncthreads();   // [A] Qt loaded (1st iter) / prev PV done before KV overwrite
        // Load K transposed + V natural
        {
            const float4* ks = (const float4*)(kb + (size_t)(j0 + lr) * DHEAD + ld0);
#pragma unroll
            for (int u = 0; u < 4; u++) {
                float4 t4 = ks[u];
                int d = ld0 + (u << 2);
                Kt[(d + 0) * PADT + lr] = t4.x;
                Kt[(d + 1) * PADT + lr] = t4.y;
                Kt[(d + 2) * PADT + lr] = t4.z;
                Kt[(d + 3) * PADT + lr] = t4.w;
            }
            const float4* vg = (const float4*)(vb + (size_t)(j0 + lr) * DHEAD + ld0);
            float4* vd = (float4*)&Vs[lr * PADT + ld0];
#pragma unroll
            for (int u = 0; u < 4; u++) vd[u] = vg[u];
        }
        __syncthreads();   // [B] tiles ready

        // S = (scaled Q) K^T
        float s[4][4];
#pragma unroll
        for (int i = 0; i < 4; i++)
#pragma unroll
            for (int j = 0; j < 4; j++) s[i][j] = 0.f;
#pragma unroll
        for (int d = 0; d < 64; d++) {
            float4 a4 = *(const float4*)&Qt[d * PADT + r0];
            float4 b4 = *(const float4*)&Kt[d * PADT + c0];
            s[0][0] += a4.x * b4.x; s[0][1] += a4.x * b4.y; s[0][2] += a4.x * b4.z; s[0][3] += a4.x * b4.w;
            s[1][0] += a4.y * b4.x; s[1][1] += a4.y * b4.y; s[1][2] += a4.y * b4.z; s[1][3] += a4.y * b4.w;
            s[2][0] += a4.z * b4.x; s[2][1] += a4.z * b4.y; s[2][2] += a4.z * b4.z; s[2][3] += a4.z * b4.w;
            s[3][0] += a4.w * b4.x; s[3][1] += a4.w * b4.y; s[3][2] += a4.w * b4.z; s[3][3] += a4.w * b4.w;
        }

        // + relative position bias (idx gather; bias row L1-resident)
#pragma unroll
        for (int i = 0; i < 4; i++) {
            const int4 idx4 = *(const int4*)&idxs[(size_t)(i0 + r0 + i) * NSEQ + j0 + c0];
            s[i][0] += __ldg(&brow[idx4.x]);
            s[i][1] += __ldg(&brow[idx4.y]);
            s[i][2] += __ldg(&brow[idx4.z]);
            s[i][3] += __ldg(&brow[idx4.w]);
        }

        // Online softmax (reductions over 16-lane row groups via shfl.xor)
#pragma unroll
        for (int i = 0; i < 4; i++) {
            float tm = fmaxf(fmaxf(s[i][0], s[i][1]), fmaxf(s[i][2], s[i][3]));
#pragma unroll
            for (int off = 8; off >= 1; off >>= 1)
                tm = fmaxf(tm, __shfl_xor_sync(0xFFFFFFFFu, tm, off));
            const float mnew = fmaxf(mrow[i], tm);
            const float sc = __expf(mrow[i] - mnew);
            mrow[i] = mnew;
            float rs = 0.f;
#pragma unroll
            for (int j = 0; j < 4; j++) {
                s[i][j] = __expf(s[i][j] - mnew);
                rs += s[i][j];
            }
#pragma unroll
            for (int off = 8; off >= 1; off >>= 1)
                rs += __shfl_xor_sync(0xFFFFFFFFu, rs, off);
            lrow[i] = lrow[i] * sc + rs;
#pragma unroll
            for (int j = 0; j < 4; j++) acc[i][j] *= sc;
        }

        __syncthreads();   // [C] everyone done reading Kt before P^T overwrites it
#pragma unroll
        for (int j = 0; j < 4; j++)
#pragma unroll
            for (int i = 0; i < 4; i++)
                Pt[(c0 + j) * PADP + r0 + i] = s[i][j];
        __syncthreads();   // [E] P^T ready

        // O += P V
#pragma unroll
        for (int c = 0; c < 64; c++) {
            const float a0 = Pt[c * PADP + r0 + 0];
            const float a1 = Pt[c * PADP + r0 + 1];
            const float a2 = Pt[c * PADP + r0 + 2];
            const float a3 = Pt[c * PADP + r0 + 3];
            const float4 v4 = *(const float4*)&Vs[c * PADT + c0];
            acc[0][0] += a0 * v4.x; acc[0][1] += a0 * v4.y; acc[0][2] += a0 * v4.z; acc[0][3] += a0 * v4.w;
            acc[1][0] += a1 * v4.x; acc[1][1] += a1 * v4.y; acc[1][2] += a1 * v4.z; acc[1][3] += a1 * v4.w;
            acc[2][0] += a2 * v4.x; acc[2][1] += a2 * v4.y; acc[2][2] += a2 * v4.z; acc[2][3] += a2 * v4.w;
            acc[3][0] += a3 * v4.x; acc[3][1] += a3 * v4.y; acc[3][2] += a3 * v4.z; acc[3][3] += a3 * v4.w;
        }
    }

    // Normalize + write to head-merged layout [b, n, h*64+d]
#pragma unroll
    for (int i = 0; i < 4; i++) {
        const float inv = 1.f / lrow[i];
        float4 o;
        o.x = acc[i][0] * inv;
        o.y = acc[i][1] * inv;
        o.z = acc[i][2] * inv;
        o.w = acc[i][3] * inv;
        *(float4*)&g_att[((size_t)(b * NSEQ) + i0 + r0 + i) * EMBD + h * DHEAD + c0] = o;
    }
}

// ---------------------------------------------------------------------------
extern "C" void kernel_launch(void* const* d_in, const int* in_sizes, int n_in,
                              void* d_out, int out_size) {
    (void)in_sizes; (void)n_in; (void)out_size;
    const float* x      = (const float*)d_in[0];
    const float* W_qkv  = (const float*)d_in[1];
    const float* biases = (const float*)d_in[2];
    const int*   idxs   = (const int*)d_in[3];
    const float* W_out  = (const float*)d_in[4];
    const float* b_out  = (const float*)d_in[5];
    float* out = (float*)d_out;

    const int attn_smem = 3 * 64 * PADT * (int)sizeof(float);  // 52224 B
    cudaFuncSetAttribute(attn_kernel, cudaFuncAttributeMaxDynamicSharedMemorySize,
                         attn_smem);

    qkv_gemm<<<dim3(24, 64), 256>>>(x, W_qkv);
    attn_kernel<<<dim3(16, BATCHX * HEADS), 256, attn_smem>>>(biases, idxs);
    out_gemm<<<dim3(8, 64), 256>>>(W_out, b_out, out);
}